// round 7
// baseline (speedup 1.0000x reference)
#include <cuda_runtime.h>
#include <cuda_bf16.h>
#include <cstdint>

// Problem constants
static constexpr int BATCH = 8;
static constexpr int SEQ   = 2048;
static constexpr int DIM   = 768;
static constexpr long long BSD = (long long)BATCH * SEQ * DIM;

// Scratch (device globals: allocation-free per harness rules). 16B-aligned for cp.async.
__device__ __align__(16) float g_xtf[BATCH * SEQ * DIM];      // x, tf32-rounded
__device__ __align__(16) float g_wtf[3 * DIM * DIM];          // w, tf32-rounded
__device__ __align__(16) float g_qkv[3 * BATCH * SEQ * DIM];  // q|k|v (tf32-rounded)
__device__ __align__(16) float g_s[BATCH * SEQ * SEQ];        // scores / attn

__device__ __forceinline__ uint32_t f2tf32(float f) {
    uint32_t u;
    asm volatile("cvt.rna.tf32.f32 %0, %1;" : "=r"(u) : "f"(f));
    return u;
}
__device__ __forceinline__ float rna(float f) { return __uint_as_float(f2tf32(f)); }

__device__ __forceinline__ void mma_tf32(
    float& c0, float& c1, float& c2, float& c3,
    uint32_t a0, uint32_t a1, uint32_t a2, uint32_t a3,
    uint32_t b0, uint32_t b1)
{
    asm volatile(
        "mma.sync.aligned.m16n8k8.row.col.f32.tf32.tf32.f32 "
        "{%0,%1,%2,%3}, {%4,%5,%6,%7}, {%8,%9}, {%0,%1,%2,%3};\n"
        : "+f"(c0), "+f"(c1), "+f"(c2), "+f"(c3)
        : "r"(a0), "r"(a1), "r"(a2), "r"(a3), "r"(b0), "r"(b1));
}

__device__ __forceinline__ void cp16(void* smem_dst, const void* gsrc) {
    uint32_t sa = (uint32_t)__cvta_generic_to_shared(smem_dst);
    asm volatile("cp.async.cg.shared.global [%0], [%1], 16;\n" :: "r"(sa), "l"(gsrc));
}

// ---------------------------------------------------------------------------
// tf32 tensor-core GEMM, 3-stage cp.async pipeline: C = alpha * A @ B(^T)
// Inputs MUST already be tf32-rounded fp32 (no CVT in consumer loop).
//   A: [M,K] row-major; B: NN -> [K,N], NT -> [N,K]; C: [M,N]
// M % 256 == 0; N % 128 == 0; K % 32 == 0.
// CTA tile 256x128x32, 512 threads / 16 warps (4m x 4n), warp tile 64x32.
//   As  [m][k]  stride 36 ; BsNN [k][n] stride 136 ; BsNT [n][k] stride 36
// R7: bigger M-tile cuts L2 read traffic per output by 25%; pipeline order is
// load -> commit -> wait_group(2) so 3 tiles are in flight before blocking.
// ---------------------------------------------------------------------------
#define BM 256
#define BN 128
#define BK 32
#define STAGES 3

static constexpr int AS_STRIDE = BK + 4;                 // 36
static constexpr int ASZ = BM * AS_STRIDE;               // 9216 floats per A stage
template <bool BT> struct BDims {
    static constexpr int STRIDE = BT ? (BK + 4) : (BN + 8);
    static constexpr int SZ     = BT ? (BN * (BK + 4)) : (BK * (BN + 8));
};

template <bool BT, bool ROUND>
__global__ __launch_bounds__(512, 1) void mma_gemm(
    const float* __restrict__ Ab, const float* __restrict__ Bb,
    float* __restrict__ Cb,
    int M, int N, int K,
    long long sA, long long sB, long long sC, float alpha)
{
    constexpr int BS_STRIDE = BDims<BT>::STRIDE;
    constexpr int BSZ       = BDims<BT>::SZ;

    const float* A = Ab + (long long)blockIdx.z * sA;
    const float* B = Bb + (long long)blockIdx.z * sB;
    float*       C = Cb + (long long)blockIdx.z * sC;

    extern __shared__ float smem[];
    float* AsBase = smem;
    float* BsBase = smem + STAGES * ASZ;

    const int tid  = threadIdx.x;
    const int warp = tid >> 5;
    const int lane = tid & 31;
    const int gid  = lane >> 2;   // 0..7
    const int tig  = lane & 3;    // 0..3
    const int wm   = (warp >> 2) * 64;   // 0,64,128,192
    const int wn   = (warp & 3) * 32;    // 0,32,64,96
    const int row0 = blockIdx.y * BM;
    const int col0 = blockIdx.x * BN;

    float c[4][4][4];
#pragma unroll
    for (int i = 0; i < 4; i++)
#pragma unroll
        for (int j = 0; j < 4; j++)
#pragma unroll
            for (int r = 0; r < 4; r++) c[i][j][r] = 0.f;

    // Loader indices (512 threads)
    const int aR = tid >> 3;            // 0..63 (+64/pass), 16B along k
    const int aC = (tid & 7) * 4;
    const int bR = tid >> 5;            // 0..15 (+16/pass), 16B along n (NN)
    const int bC = (tid & 31) * 4;

    auto load_tile = [&](int stage, int kt) {
        float* As = AsBase + stage * ASZ;
        float* Bs = BsBase + stage * BSZ;
#pragma unroll
        for (int p = 0; p < 4; p++) {       // A: 256 rows
            int r = aR + p * 64;
            cp16(&As[r * AS_STRIDE + aC], A + (long long)(row0 + r) * K + kt + aC);
        }
        if (BT) {
#pragma unroll
            for (int p = 0; p < 2; p++) {   // B NT: 128 rows
                int r = aR + p * 64;
                cp16(&Bs[r * BS_STRIDE + aC], B + (long long)(col0 + r) * K + kt + aC);
            }
        } else {
#pragma unroll
            for (int p = 0; p < 2; p++) {   // B NN: 32 rows x 128 cols
                int r = bR + p * 16;
                cp16(&Bs[r * BS_STRIDE + bC], B + (long long)(kt + r) * N + col0 + bC);
            }
        }
    };

    const int T = K / BK;
    load_tile(0, 0);
    asm volatile("cp.async.commit_group;\n");
    load_tile(1, BK);
    asm volatile("cp.async.commit_group;\n");

    for (int t = 0; t < T; t++) {
        // Issue next tile's loads BEFORE blocking (3 tiles in flight).
        int nt = t + 2;
        if (nt < T) load_tile(nt % STAGES, nt * BK);
        asm volatile("cp.async.commit_group;\n");
        asm volatile("cp.async.wait_group 2;\n");   // tile t complete
        __syncthreads();

        const uint32_t* As = (const uint32_t*)(AsBase + (t % STAGES) * ASZ);
        const uint32_t* Bs = (const uint32_t*)(BsBase + (t % STAGES) * BSZ);

#pragma unroll
        for (int ks = 0; ks < BK; ks += 8) {
            uint32_t a[4][4];
#pragma unroll
            for (int i = 0; i < 4; i++) {
                int m = wm + 16 * i + gid;
                a[i][0] = As[m * AS_STRIDE + ks + tig];
                a[i][1] = As[(m + 8) * AS_STRIDE + ks + tig];
                a[i][2] = As[m * AS_STRIDE + ks + tig + 4];
                a[i][3] = As[(m + 8) * AS_STRIDE + ks + tig + 4];
            }
            uint32_t b[4][2];
#pragma unroll
            for (int j = 0; j < 4; j++) {
                int n = wn + 8 * j + gid;
                if (BT) {
                    b[j][0] = Bs[n * BS_STRIDE + ks + tig];
                    b[j][1] = Bs[n * BS_STRIDE + ks + tig + 4];
                } else {
                    b[j][0] = Bs[(ks + tig) * BS_STRIDE + n];
                    b[j][1] = Bs[(ks + tig + 4) * BS_STRIDE + n];
                }
            }
#pragma unroll
            for (int i = 0; i < 4; i++)
#pragma unroll
                for (int j = 0; j < 4; j++)
                    mma_tf32(c[i][j][0], c[i][j][1], c[i][j][2], c[i][j][3],
                             a[i][0], a[i][1], a[i][2], a[i][3],
                             b[j][0], b[j][1]);
        }
        __syncthreads();
    }

#pragma unroll
    for (int i = 0; i < 4; i++) {
        int rowA = row0 + wm + 16 * i + gid;
#pragma unroll
        for (int j = 0; j < 4; j++) {
            int col = col0 + wn + 8 * j + 2 * tig;
            float f0 = c[i][j][0] * alpha, f1 = c[i][j][1] * alpha;
            float f2 = c[i][j][2] * alpha, f3 = c[i][j][3] * alpha;
            if (ROUND) { f0 = rna(f0); f1 = rna(f1); f2 = rna(f2); f3 = rna(f3); }
            *(float2*)(C + (long long)rowA * N + col) = make_float2(f0, f1);
            *(float2*)(C + (long long)(rowA + 8) * N + col) = make_float2(f2, f3);
        }
    }
}

// ---------------------------------------------------------------------------
// Elementwise tf32 rounding (prep)
// ---------------------------------------------------------------------------
__global__ __launch_bounds__(256) void cvt_rna_kernel(
    const float* __restrict__ in, float* __restrict__ out)
{
    int i = (blockIdx.x * 256 + threadIdx.x) * 4;
    float4 v = *(const float4*)(in + i);
    v.x = rna(v.x); v.y = rna(v.y); v.z = rna(v.z); v.w = rna(v.w);
    *(float4*)(out + i) = v;
}

// ---------------------------------------------------------------------------
// Row softmax over 2048 columns; writes tf32-rounded probabilities
// ---------------------------------------------------------------------------
__global__ __launch_bounds__(256) void softmax2048(float* __restrict__ S)
{
    float* row = S + (long long)blockIdx.x * SEQ;
    const int tid = threadIdx.x;

    float x[8];
#pragma unroll
    for (int i = 0; i < 8; i++) x[i] = row[i * 256 + tid];

    float m = x[0];
#pragma unroll
    for (int i = 1; i < 8; i++) m = fmaxf(m, x[i]);
#pragma unroll
    for (int o = 16; o > 0; o >>= 1)
        m = fmaxf(m, __shfl_xor_sync(0xffffffffu, m, o));

    __shared__ float red[8];
    if ((tid & 31) == 0) red[tid >> 5] = m;
    __syncthreads();
    float mAll = red[0];
#pragma unroll
    for (int i = 1; i < 8; i++) mAll = fmaxf(mAll, red[i]);
    __syncthreads();

    float s = 0.f;
#pragma unroll
    for (int i = 0; i < 8; i++) {
        x[i] = __expf(x[i] - mAll);
        s += x[i];
    }
#pragma unroll
    for (int o = 16; o > 0; o >>= 1)
        s += __shfl_xor_sync(0xffffffffu, s, o);
    if ((tid & 31) == 0) red[tid >> 5] = s;
    __syncthreads();
    float tot = 0.f;
#pragma unroll
    for (int i = 0; i < 8; i++) tot += red[i];

    const float inv = 1.f / tot;
#pragma unroll
    for (int i = 0; i < 8; i++) row[i * 256 + tid] = rna(x[i] * inv);
}

// ---------------------------------------------------------------------------
// Launch
// ---------------------------------------------------------------------------
extern "C" void kernel_launch(void* const* d_in, const int* in_sizes, int n_in,
                              void* d_out, int out_size)
{
    const float* x = (const float*)d_in[0];   // [8, 2048, 768]
    const float* w = (const float*)d_in[1];   // [3, 768, 768]
    float* out     = (float*)d_out;           // [8, 2048, 768]

    float *xtf, *wtf, *qkv, *sc;
    cudaGetSymbolAddress((void**)&xtf, g_xtf);
    cudaGetSymbolAddress((void**)&wtf, g_wtf);
    cudaGetSymbolAddress((void**)&qkv, g_qkv);
    cudaGetSymbolAddress((void**)&sc,  g_s);

    const float INV_SCALE = 0.125f;  // 1 / sqrt(64)

    constexpr int SMEM_NN = STAGES * (ASZ + BDims<false>::SZ) * 4;  // 162,816 B
    constexpr int SMEM_NT = STAGES * (ASZ + BDims<true>::SZ) * 4;   // 165,888 B

    cudaFuncSetAttribute(mma_gemm<false, true>,
                         cudaFuncAttributeMaxDynamicSharedMemorySize, SMEM_NN);
    cudaFuncSetAttribute(mma_gemm<false, false>,
                         cudaFuncAttributeMaxDynamicSharedMemorySize, SMEM_NN);
    cudaFuncSetAttribute(mma_gemm<true, false>,
                         cudaFuncAttributeMaxDynamicSharedMemorySize, SMEM_NT);

    // 0) Pre-round x and w to tf32 (no CVT in GEMM hot loops)
    cvt_rna_kernel<<<(BATCH * SEQ * DIM) / 1024, 256>>>(x, xtf);
    cvt_rna_kernel<<<(3 * DIM * DIM) / 1024, 256>>>(w, wtf);

    // 1) QKV projection: [16384,768] @ [768,768] per weight slice (z=3);
    //    outputs rounded to tf32 so stages 2/4 need no CVT.
    {
        dim3 grid(DIM / BN, (BATCH * SEQ) / BM, 3);
        mma_gemm<false, true><<<grid, 512, SMEM_NN>>>(xtf, wtf, qkv,
                                       BATCH * SEQ, DIM, DIM,
                                       0LL, (long long)DIM * DIM, BSD, 1.0f);
    }

    // 2) scores = Q @ K^T / 8  (batched over 8); output stays fp32 for softmax
    {
        dim3 grid(SEQ / BN, SEQ / BM, BATCH);
        mma_gemm<true, false><<<grid, 512, SMEM_NT>>>(qkv, qkv + BSD, sc,
                                      SEQ, SEQ, DIM,
                                      (long long)SEQ * DIM, (long long)SEQ * DIM,
                                      (long long)SEQ * SEQ, INV_SCALE);
    }

    // 3) softmax over last dim; writes tf32-rounded attn
    softmax2048<<<BATCH * SEQ, 256>>>(sc);

    // 4) out = attn @ V  (batched over 8)
    {
        dim3 grid(DIM / BN, SEQ / BM, BATCH);
        mma_gemm<false, false><<<grid, 512, SMEM_NN>>>(sc, qkv + 2 * BSD, out,
                                       SEQ, DIM, SEQ,
                                       (long long)SEQ * SEQ, (long long)SEQ * DIM,
                                       (long long)SEQ * DIM, 1.0f);
    }
}

// round 8
// speedup vs baseline: 1.0649x; 1.0649x over previous
#include <cuda_runtime.h>
#include <cuda_bf16.h>
#include <cstdint>

// Problem constants
static constexpr int BATCH = 8;
static constexpr int SEQ   = 2048;
static constexpr int DIM   = 768;
static constexpr long long BSD = (long long)BATCH * SEQ * DIM;

// Scratch (device globals: allocation-free per harness rules). 16B-aligned for cp.async.
__device__ __align__(16) float g_xtf[BATCH * SEQ * DIM];      // x, tf32-rounded
__device__ __align__(16) float g_wtf[3 * DIM * DIM];          // w, tf32-rounded
__device__ __align__(16) float g_qkv[3 * BATCH * SEQ * DIM];  // q|k|v (tf32-rounded)
__device__ __align__(16) float g_s[BATCH * SEQ * SEQ];        // scores / attn

__device__ __forceinline__ uint32_t f2tf32(float f) {
    uint32_t u;
    asm volatile("cvt.rna.tf32.f32 %0, %1;" : "=r"(u) : "f"(f));
    return u;
}
__device__ __forceinline__ float rna(float f) { return __uint_as_float(f2tf32(f)); }

__device__ __forceinline__ void mma_tf32(
    float& c0, float& c1, float& c2, float& c3,
    uint32_t a0, uint32_t a1, uint32_t a2, uint32_t a3,
    uint32_t b0, uint32_t b1)
{
    asm volatile(
        "mma.sync.aligned.m16n8k8.row.col.f32.tf32.tf32.f32 "
        "{%0,%1,%2,%3}, {%4,%5,%6,%7}, {%8,%9}, {%0,%1,%2,%3};\n"
        : "+f"(c0), "+f"(c1), "+f"(c2), "+f"(c3)
        : "r"(a0), "r"(a1), "r"(a2), "r"(a3), "r"(b0), "r"(b1));
}

__device__ __forceinline__ void cp16(void* smem_dst, const void* gsrc) {
    uint32_t sa = (uint32_t)__cvta_generic_to_shared(smem_dst);
    asm volatile("cp.async.cg.shared.global [%0], [%1], 16;\n" :: "r"(sa), "l"(gsrc));
}

// ---------------------------------------------------------------------------
// tf32 tensor-core GEMM, 3-stage cp.async pipeline: C = alpha * A @ B(^T)
// Inputs MUST already be tf32-rounded fp32 (no CVT in consumer loop).
//   A: [M,K] row-major; B: NN -> [K,N], NT -> [N,K]; C: [M,N]
// M,N % 128 == 0; K % 32 == 0.
// CTA 128x128x32, 8 warps (2x4), warp tile 64x32, mma m16n8k8.
//   As  [m][k]  stride 36 ; BsNN [k][n] stride 136 ; BsNT [n][k] stride 36
// __launch_bounds__(256, 2): 2 CTAs/SM (R6/R7 evidence: cross-CTA overlap
// beats bigger tiles). R8: load tile t+2 BEFORE wait_group so 3 tiles are in
// flight at the blocking point (per CTA; 6 per SM).
// ---------------------------------------------------------------------------
#define BM 128
#define BN 128
#define BK 32
#define STAGES 3

static constexpr int AS_STRIDE = BK + 4;                 // 36
static constexpr int ASZ = BM * AS_STRIDE;               // floats per A stage
template <bool BT> struct BDims {
    static constexpr int STRIDE = BT ? (BK + 4) : (BN + 8);
    static constexpr int SZ     = BT ? (BN * (BK + 4)) : (BK * (BN + 8));
};

template <bool BT, bool ROUND>
__global__ __launch_bounds__(256, 2) void mma_gemm(
    const float* __restrict__ Ab, const float* __restrict__ Bb,
    float* __restrict__ Cb,
    int M, int N, int K,
    long long sA, long long sB, long long sC, float alpha)
{
    constexpr int BS_STRIDE = BDims<BT>::STRIDE;
    constexpr int BSZ       = BDims<BT>::SZ;

    const float* A = Ab + (long long)blockIdx.z * sA;
    const float* B = Bb + (long long)blockIdx.z * sB;
    float*       C = Cb + (long long)blockIdx.z * sC;

    extern __shared__ float smem[];
    float* AsBase = smem;
    float* BsBase = smem + STAGES * ASZ;

    const int tid  = threadIdx.x;
    const int warp = tid >> 5;
    const int lane = tid & 31;
    const int gid  = lane >> 2;   // 0..7
    const int tig  = lane & 3;    // 0..3
    const int wm   = (warp >> 2) * 64;
    const int wn   = (warp & 3) * 32;
    const int row0 = blockIdx.y * BM;
    const int col0 = blockIdx.x * BN;

    float c[4][4][4];
#pragma unroll
    for (int i = 0; i < 4; i++)
#pragma unroll
        for (int j = 0; j < 4; j++)
#pragma unroll
            for (int r = 0; r < 4; r++) c[i][j][r] = 0.f;

    const int aR = tid >> 3;            // 0..31 (+32/pass), 16B along k
    const int aC = (tid & 7) * 4;
    const int bR = tid >> 5;            // 0..7 (+8/pass), 16B along n (NN)
    const int bC = (tid & 31) * 4;

    auto load_tile = [&](int stage, int kt) {
        float* As = AsBase + stage * ASZ;
        float* Bs = BsBase + stage * BSZ;
#pragma unroll
        for (int p = 0; p < 4; p++) {
            int r = aR + p * 32;
            cp16(&As[r * AS_STRIDE + aC], A + (long long)(row0 + r) * K + kt + aC);
        }
        if (BT) {
#pragma unroll
            for (int p = 0; p < 4; p++) {
                int r = aR + p * 32;
                cp16(&Bs[r * BS_STRIDE + aC], B + (long long)(col0 + r) * K + kt + aC);
            }
        } else {
#pragma unroll
            for (int p = 0; p < 4; p++) {
                int r = bR + p * 8;
                cp16(&Bs[r * BS_STRIDE + bC], B + (long long)(kt + r) * N + col0 + bC);
            }
        }
    };

    const int T = K / BK;
    load_tile(0, 0);
    asm volatile("cp.async.commit_group;\n");
    load_tile(1, BK);
    asm volatile("cp.async.commit_group;\n");

    for (int t = 0; t < T; t++) {
        // Issue tile t+2's loads BEFORE blocking: 3 tiles in flight.
        int nt = t + 2;
        if (nt < T) load_tile(nt % STAGES, nt * BK);
        asm volatile("cp.async.commit_group;\n");
        asm volatile("cp.async.wait_group 2;\n");   // tile t complete
        __syncthreads();

        const uint32_t* As = (const uint32_t*)(AsBase + (t % STAGES) * ASZ);
        const uint32_t* Bs = (const uint32_t*)(BsBase + (t % STAGES) * BSZ);

#pragma unroll
        for (int ks = 0; ks < BK; ks += 8) {
            uint32_t a[4][4];
#pragma unroll
            for (int i = 0; i < 4; i++) {
                int m = wm + 16 * i + gid;
                a[i][0] = As[m * AS_STRIDE + ks + tig];
                a[i][1] = As[(m + 8) * AS_STRIDE + ks + tig];
                a[i][2] = As[m * AS_STRIDE + ks + tig + 4];
                a[i][3] = As[(m + 8) * AS_STRIDE + ks + tig + 4];
            }
            uint32_t b[4][2];
#pragma unroll
            for (int j = 0; j < 4; j++) {
                int n = wn + 8 * j + gid;
                if (BT) {
                    b[j][0] = Bs[n * BS_STRIDE + ks + tig];
                    b[j][1] = Bs[n * BS_STRIDE + ks + tig + 4];
                } else {
                    b[j][0] = Bs[(ks + tig) * BS_STRIDE + n];
                    b[j][1] = Bs[(ks + tig + 4) * BS_STRIDE + n];
                }
            }
#pragma unroll
            for (int i = 0; i < 4; i++)
#pragma unroll
                for (int j = 0; j < 4; j++)
                    mma_tf32(c[i][j][0], c[i][j][1], c[i][j][2], c[i][j][3],
                             a[i][0], a[i][1], a[i][2], a[i][3],
                             b[j][0], b[j][1]);
        }
        __syncthreads();
    }

#pragma unroll
    for (int i = 0; i < 4; i++) {
        int rowA = row0 + wm + 16 * i + gid;
#pragma unroll
        for (int j = 0; j < 4; j++) {
            int col = col0 + wn + 8 * j + 2 * tig;
            float f0 = c[i][j][0] * alpha, f1 = c[i][j][1] * alpha;
            float f2 = c[i][j][2] * alpha, f3 = c[i][j][3] * alpha;
            if (ROUND) { f0 = rna(f0); f1 = rna(f1); f2 = rna(f2); f3 = rna(f3); }
            *(float2*)(C + (long long)rowA * N + col) = make_float2(f0, f1);
            *(float2*)(C + (long long)(rowA + 8) * N + col) = make_float2(f2, f3);
        }
    }
}

// ---------------------------------------------------------------------------
// Elementwise tf32 rounding (prep)
// ---------------------------------------------------------------------------
__global__ __launch_bounds__(256) void cvt_rna_kernel(
    const float* __restrict__ in, float* __restrict__ out)
{
    int i = (blockIdx.x * 256 + threadIdx.x) * 4;
    float4 v = *(const float4*)(in + i);
    v.x = rna(v.x); v.y = rna(v.y); v.z = rna(v.z); v.w = rna(v.w);
    *(float4*)(out + i) = v;
}

// ---------------------------------------------------------------------------
// Row softmax over 2048 columns; writes tf32-rounded probabilities
// ---------------------------------------------------------------------------
__global__ __launch_bounds__(256) void softmax2048(float* __restrict__ S)
{
    float* row = S + (long long)blockIdx.x * SEQ;
    const int tid = threadIdx.x;

    float x[8];
#pragma unroll
    for (int i = 0; i < 8; i++) x[i] = row[i * 256 + tid];

    float m = x[0];
#pragma unroll
    for (int i = 1; i < 8; i++) m = fmaxf(m, x[i]);
#pragma unroll
    for (int o = 16; o > 0; o >>= 1)
        m = fmaxf(m, __shfl_xor_sync(0xffffffffu, m, o));

    __shared__ float red[8];
    if ((tid & 31) == 0) red[tid >> 5] = m;
    __syncthreads();
    float mAll = red[0];
#pragma unroll
    for (int i = 1; i < 8; i++) mAll = fmaxf(mAll, red[i]);
    __syncthreads();

    float s = 0.f;
#pragma unroll
    for (int i = 0; i < 8; i++) {
        x[i] = __expf(x[i] - mAll);
        s += x[i];
    }
#pragma unroll
    for (int o = 16; o > 0; o >>= 1)
        s += __shfl_xor_sync(0xffffffffu, s, o);
    if ((tid & 31) == 0) red[tid >> 5] = s;
    __syncthreads();
    float tot = 0.f;
#pragma unroll
    for (int i = 0; i < 8; i++) tot += red[i];

    const float inv = 1.f / tot;
#pragma unroll
    for (int i = 0; i < 8; i++) row[i * 256 + tid] = rna(x[i] * inv);
}

// ---------------------------------------------------------------------------
// Launch
// ---------------------------------------------------------------------------
extern "C" void kernel_launch(void* const* d_in, const int* in_sizes, int n_in,
                              void* d_out, int out_size)
{
    const float* x = (const float*)d_in[0];   // [8, 2048, 768]
    const float* w = (const float*)d_in[1];   // [3, 768, 768]
    float* out     = (float*)d_out;           // [8, 2048, 768]

    float *xtf, *wtf, *qkv, *sc;
    cudaGetSymbolAddress((void**)&xtf, g_xtf);
    cudaGetSymbolAddress((void**)&wtf, g_wtf);
    cudaGetSymbolAddress((void**)&qkv, g_qkv);
    cudaGetSymbolAddress((void**)&sc,  g_s);

    const float INV_SCALE = 0.125f;  // 1 / sqrt(64)

    constexpr int SMEM_NN = STAGES * (ASZ + BDims<false>::SZ) * 4;  // 107,520 B
    constexpr int SMEM_NT = STAGES * (ASZ + BDims<true>::SZ) * 4;   // 110,592 B

    cudaFuncSetAttribute(mma_gemm<false, true>,
                         cudaFuncAttributeMaxDynamicSharedMemorySize, SMEM_NN);
    cudaFuncSetAttribute(mma_gemm<false, false>,
                         cudaFuncAttributeMaxDynamicSharedMemorySize, SMEM_NN);
    cudaFuncSetAttribute(mma_gemm<true, false>,
                         cudaFuncAttributeMaxDynamicSharedMemorySize, SMEM_NT);

    // 0) Pre-round x and w to tf32 (no CVT in GEMM hot loops)
    cvt_rna_kernel<<<(BATCH * SEQ * DIM) / 1024, 256>>>(x, xtf);
    cvt_rna_kernel<<<(3 * DIM * DIM) / 1024, 256>>>(w, wtf);

    // 1) QKV projection: [16384,768] @ [768,768] per weight slice (z=3);
    //    outputs rounded to tf32 so stages 2/4 need no CVT.
    {
        dim3 grid(DIM / BN, (BATCH * SEQ) / BM, 3);
        mma_gemm<false, true><<<grid, 256, SMEM_NN>>>(xtf, wtf, qkv,
                                       BATCH * SEQ, DIM, DIM,
                                       0LL, (long long)DIM * DIM, BSD, 1.0f);
    }

    // 2) scores = Q @ K^T / 8  (batched over 8); output stays fp32 for softmax
    {
        dim3 grid(SEQ / BN, SEQ / BM, BATCH);
        mma_gemm<true, false><<<grid, 256, SMEM_NT>>>(qkv, qkv + BSD, sc,
                                      SEQ, SEQ, DIM,
                                      (long long)SEQ * DIM, (long long)SEQ * DIM,
                                      (long long)SEQ * SEQ, INV_SCALE);
    }

    // 3) softmax over last dim; writes tf32-rounded attn
    softmax2048<<<BATCH * SEQ, 256>>>(sc);

    // 4) out = attn @ V  (batched over 8)
    {
        dim3 grid(DIM / BN, SEQ / BM, BATCH);
        mma_gemm<false, false><<<grid, 256, SMEM_NN>>>(sc, qkv + 2 * BSD, out,
                                       SEQ, DIM, SEQ,
                                       (long long)SEQ * SEQ, (long long)SEQ * DIM,
                                       (long long)SEQ * DIM, 1.0f);
    }
}